// round 4
// baseline (speedup 1.0000x reference)
#include <cuda_runtime.h>
#include <cuda_fp16.h>
#include <math.h>

#define NB 64
#define NS 512
#define NH 768
#define NC 50
#define NM 2000
#define NT (NB*NS)   // 32768

#define MCAP 2048    // per-mention active-token capacity (expect ~327)
#define UCAP 4096    // per-char utterance active capacity (expect ~655)
#define SCAP 512     // per-char mention-segment capacity (expect ~44)

#define NEGINF (__int_as_float(0xff800000))

// ---------------- scratch (device globals; no allocation) ----------------
__device__ float g_nts[NT];
__device__ float g_mts[NT];
__device__ float g_uts[NT];

__device__ __half g_se_h[(size_t)NT*NH];         // 50 MB fp16 copy of story

__device__ float g_names_emb[(size_t)NC*NB*NH];  // 9.8 MB
__device__ float g_nscore[NC*NB];
__device__ float g_name_e[NC*NH];

__device__ float g_memb[(size_t)NM*NH];          // 6.1 MB
__device__ float g_mscore[NM];

__device__ float g_utt_e[NC*NH];
__device__ int   g_has_utt[NC];

// ---------------- block reductions (any blockDim multiple of 32, <=1024) ----------------
__device__ __forceinline__ float blockReduceSum(float v) {
    __shared__ float sh[32];
    __shared__ float res;
    int lane = threadIdx.x & 31, wid = threadIdx.x >> 5, nw = blockDim.x >> 5;
    #pragma unroll
    for (int o = 16; o; o >>= 1) v += __shfl_xor_sync(0xffffffffu, v, o);
    if (lane == 0) sh[wid] = v;
    __syncthreads();
    if (threadIdx.x == 0) {
        float s = 0.f;
        for (int i = 0; i < nw; i++) s += sh[i];
        res = s;
    }
    __syncthreads();
    return res;
}

__device__ __forceinline__ float blockReduceMax(float v) {
    __shared__ float sh[32];
    __shared__ float res;
    int lane = threadIdx.x & 31, wid = threadIdx.x >> 5, nw = blockDim.x >> 5;
    #pragma unroll
    for (int o = 16; o; o >>= 1) v = fmaxf(v, __shfl_xor_sync(0xffffffffu, v, o));
    if (lane == 0) sh[wid] = v;
    __syncthreads();
    if (threadIdx.x == 0) {
        float s = NEGINF;
        for (int i = 0; i < nw; i++) s = fmaxf(s, sh[i]);
        res = s;
    }
    __syncthreads();
    return res;
}

// ---------------- K1: fused token projections + fp16 copy ----------------
__global__ void k_proj(const float* __restrict__ se,
                       const float* __restrict__ w_nt, const float* __restrict__ b_nt,
                       const float* __restrict__ w_mt, const float* __restrict__ b_mt,
                       const float* __restrict__ w_ut, const float* __restrict__ b_ut) {
    int warp = (blockIdx.x * blockDim.x + threadIdx.x) >> 5;
    int lane = threadIdx.x & 31;
    if (warp >= NT) return;
    const float4* row = (const float4*)(se + (size_t)warp * NH);
    __half2* hrow = (__half2*)(g_se_h + (size_t)warp * NH);
    const float4* wn = (const float4*)w_nt;
    const float4* wm = (const float4*)w_mt;
    const float4* wu = (const float4*)w_ut;
    float a = 0.f, b = 0.f, c = 0.f;
    #pragma unroll
    for (int i = 0; i < 6; i++) {
        float4 x = row[lane + 32 * i];
        // fp16 side copy (coalesced 8B stores)
        __half2 h01 = __floats2half2_rn(x.x, x.y);
        __half2 h23 = __floats2half2_rn(x.z, x.w);
        hrow[2 * (lane + 32 * i)]     = h01;
        hrow[2 * (lane + 32 * i) + 1] = h23;
        float4 n = __ldg(&wn[lane + 32 * i]);
        float4 m = __ldg(&wm[lane + 32 * i]);
        float4 u = __ldg(&wu[lane + 32 * i]);
        a += x.x*n.x + x.y*n.y + x.z*n.z + x.w*n.w;
        b += x.x*m.x + x.y*m.y + x.z*m.z + x.w*m.w;
        c += x.x*u.x + x.y*u.y + x.z*u.z + x.w*u.w;
    }
    #pragma unroll
    for (int o = 16; o; o >>= 1) {
        a += __shfl_xor_sync(0xffffffffu, a, o);
        b += __shfl_xor_sync(0xffffffffu, b, o);
        c += __shfl_xor_sync(0xffffffffu, c, o);
    }
    if (lane == 0) {
        g_nts[warp] = a + __ldg(b_nt);
        g_mts[warp] = b + __ldg(b_mt);
        g_uts[warp] = c + __ldg(b_ut);
    }
}

// ---------------- K2: per-(char, block) name attention (fp16 gather) ----------------
__global__ void k_names(const float* __restrict__ nmask,
                        const float* __restrict__ w_name, const float* __restrict__ b_name) {
    int c = blockIdx.x / NB, b = blockIdx.x % NB;
    int tid = threadIdx.x;
    __shared__ int s_idx[NS];
    __shared__ float s_w[NS];
    __shared__ int s_cnt;
    if (tid == 0) s_cnt = 0;
    __syncthreads();

    float lmax = NEGINF;
    for (int s = tid; s < NS; s += 256) {
        float m = nmask[c * NS + s];
        if (m > -1e30f) {
            float sc = m + g_nts[b * NS + s];
            int p = atomicAdd(&s_cnt, 1);
            s_idx[p] = s; s_w[p] = sc;
            lmax = fmaxf(lmax, sc);
        }
    }
    lmax = blockReduceMax(lmax);          // barrier makes list writes visible
    int cnt = s_cnt;

    float lsum = 0.f;
    for (int i = tid; i < cnt; i += 256) {
        float e = expf(s_w[i] - lmax);
        s_w[i] = e; lsum += e;
    }
    float tot = blockReduceSum(lsum);
    float inv = 1.f / tot;

    const __half* blk = g_se_h + (size_t)b * NS * NH;
    float a0 = 0.f, a1 = 0.f, a2 = 0.f;
    for (int i = 0; i < cnt; i++) {
        int s = s_idx[i];
        float w = s_w[i] * inv;
        const __half* r = blk + (size_t)s * NH;
        a0 += w * __half2float(r[tid]);
        a1 += w * __half2float(r[tid + 256]);
        a2 += w * __half2float(r[tid + 512]);
    }
    size_t o = ((size_t)c * NB + b) * NH;
    g_names_emb[o + tid]       = a0;
    g_names_emb[o + tid + 256] = a1;
    g_names_emb[o + tid + 512] = a2;

    float d = a0 * __ldg(&w_name[tid]) + a1 * __ldg(&w_name[tid + 256]) + a2 * __ldg(&w_name[tid + 512]);
    d = blockReduceSum(d);
    if (tid == 0) g_nscore[c * NB + b] = d + __ldg(b_name);
}

// ---------------- K3: name_e = softmax over blocks (1024 thr, 4-way b-split) --------
__global__ void k_name_e() {
    int c = blockIdx.x, tid = threadIdx.x;
    int grp = tid >> 8, gtid = tid & 255;
    __shared__ float p[NB];
    __shared__ float sp[4][NH];
    if (tid == 0) {
        float mx = NEGINF;
        for (int b = 0; b < NB; b++) mx = fmaxf(mx, g_nscore[c * NB + b]);
        float s = 0.f;
        for (int b = 0; b < NB; b++) { float e = expf(g_nscore[c * NB + b] - mx); p[b] = e; s += e; }
        float inv = 1.f / s;
        for (int b = 0; b < NB; b++) p[b] *= inv;
    }
    __syncthreads();
    float a0 = 0.f, a1 = 0.f, a2 = 0.f;
    const float* base = g_names_emb + (size_t)c * NB * NH;
    for (int b = grp; b < NB; b += 4) {
        float w = p[b];
        const float* r = base + (size_t)b * NH;
        a0 += w * r[gtid]; a1 += w * r[gtid + 256]; a2 += w * r[gtid + 512];
    }
    sp[grp][gtid] = a0; sp[grp][gtid + 256] = a1; sp[grp][gtid + 512] = a2;
    __syncthreads();
    if (tid < NH) {
        g_name_e[c * NH + tid] = sp[0][tid] + sp[1][tid] + sp[2][tid] + sp[3][tid];
    }
}

// ---------------- K4: fused mention compaction + softmax + fp16 gather (1024 thr) ----
__global__ void k_mention(const float* __restrict__ mmask,
                          const float* __restrict__ w_men, const float* __restrict__ b_men) {
    int m = blockIdx.x, tid = threadIdx.x;
    int grp = tid >> 8, gtid = tid & 255;
    __shared__ int s_idx[MCAP];
    __shared__ float s_sc[MCAP];
    __shared__ float sp[4][NH];
    __shared__ int s_cnt;
    if (tid == 0) s_cnt = 0;
    __syncthreads();

    const float4* row = (const float4*)(mmask + (size_t)m * NT);
    float lmax = NEGINF;
    for (int i = tid; i < NT / 4; i += 1024) {
        float4 v = __ldcs(row + i);
        int t0 = i * 4;
        if (v.x > -1e30f) { int p = atomicAdd(&s_cnt, 1); if (p < MCAP) { float sc = v.x + g_mts[t0];     s_idx[p] = t0;     s_sc[p] = sc; lmax = fmaxf(lmax, sc); } }
        if (v.y > -1e30f) { int p = atomicAdd(&s_cnt, 1); if (p < MCAP) { float sc = v.y + g_mts[t0 + 1]; s_idx[p] = t0 + 1; s_sc[p] = sc; lmax = fmaxf(lmax, sc); } }
        if (v.z > -1e30f) { int p = atomicAdd(&s_cnt, 1); if (p < MCAP) { float sc = v.z + g_mts[t0 + 2]; s_idx[p] = t0 + 2; s_sc[p] = sc; lmax = fmaxf(lmax, sc); } }
        if (v.w > -1e30f) { int p = atomicAdd(&s_cnt, 1); if (p < MCAP) { float sc = v.w + g_mts[t0 + 3]; s_idx[p] = t0 + 3; s_sc[p] = sc; lmax = fmaxf(lmax, sc); } }
    }
    lmax = blockReduceMax(lmax);          // barrier: list complete & visible
    int cnt = min(s_cnt, MCAP);

    float lsum = 0.f;
    for (int i = tid; i < cnt; i += 1024) {
        float e = expf(s_sc[i] - lmax);
        s_sc[i] = e; lsum += e;
    }
    float tot = blockReduceSum(lsum);     // barrier: s_sc exp values visible
    float inv = 1.f / tot;

    float a0 = 0.f, a1 = 0.f, a2 = 0.f;
    for (int i = grp; i < cnt; i += 4) {
        int t = s_idx[i];
        float w = s_sc[i] * inv;
        const __half* r = g_se_h + (size_t)t * NH;
        a0 += w * __half2float(r[gtid]);
        a1 += w * __half2float(r[gtid + 256]);
        a2 += w * __half2float(r[gtid + 512]);
    }
    sp[grp][gtid] = a0; sp[grp][gtid + 256] = a1; sp[grp][gtid + 512] = a2;
    __syncthreads();
    float d = 0.f;
    if (tid < NH) {
        float f = sp[0][tid] + sp[1][tid] + sp[2][tid] + sp[3][tid];
        g_memb[(size_t)m * NH + tid] = f;
        d = f * __ldg(&w_men[tid]);
    }
    d = blockReduceSum(d);
    if (tid == 0) g_mscore[m] = d + __ldg(b_men);
}

// ---------------- K5: utterance attention per char (1024 thr, fp16 gather) ----------
__global__ void k_utt(const float* __restrict__ umask) {
    int c = blockIdx.x, tid = threadIdx.x;
    int grp = tid >> 8, gtid = tid & 255;
    __shared__ int s_idx[UCAP];
    __shared__ float s_sc[UCAP];
    __shared__ float sp[4][NH];
    __shared__ int s_cnt;
    if (tid == 0) s_cnt = 0;
    __syncthreads();

    const float4* row = (const float4*)(umask + (size_t)c * NT);
    float lmax = NEGINF;
    for (int i = tid; i < NT / 4; i += 1024) {
        float4 v = __ldcs(row + i);
        int t0 = i * 4;
        if (v.x > -1e30f) { int p = atomicAdd(&s_cnt, 1); if (p < UCAP) { float sc = v.x + g_uts[t0];     s_idx[p] = t0;     s_sc[p] = sc; lmax = fmaxf(lmax, sc); } }
        if (v.y > -1e30f) { int p = atomicAdd(&s_cnt, 1); if (p < UCAP) { float sc = v.y + g_uts[t0 + 1]; s_idx[p] = t0 + 1; s_sc[p] = sc; lmax = fmaxf(lmax, sc); } }
        if (v.z > -1e30f) { int p = atomicAdd(&s_cnt, 1); if (p < UCAP) { float sc = v.z + g_uts[t0 + 2]; s_idx[p] = t0 + 2; s_sc[p] = sc; lmax = fmaxf(lmax, sc); } }
        if (v.w > -1e30f) { int p = atomicAdd(&s_cnt, 1); if (p < UCAP) { float sc = v.w + g_uts[t0 + 3]; s_idx[p] = t0 + 3; s_sc[p] = sc; lmax = fmaxf(lmax, sc); } }
    }
    lmax = blockReduceMax(lmax);
    int cnt = min(s_cnt, UCAP);

    if (cnt == 0) {  // no utterances: softmax is NaN -> nan_to_num -> zeros
        if (tid < NH) g_utt_e[c * NH + tid] = 0.f;
        if (tid == 0) g_has_utt[c] = 0;
        return;
    }

    float lsum = 0.f;
    for (int i = tid; i < cnt; i += 1024) {
        float e = expf(s_sc[i] - lmax);
        s_sc[i] = e; lsum += e;
    }
    float tot = blockReduceSum(lsum);
    float inv = 1.f / tot;

    float a0 = 0.f, a1 = 0.f, a2 = 0.f;
    for (int i = grp; i < cnt; i += 4) {
        int t = s_idx[i];
        float w = s_sc[i] * inv;
        const __half* r = g_se_h + (size_t)t * NH;
        a0 += w * __half2float(r[gtid]);
        a1 += w * __half2float(r[gtid + 256]);
        a2 += w * __half2float(r[gtid + 512]);
    }
    sp[grp][gtid] = a0; sp[grp][gtid + 256] = a1; sp[grp][gtid + 512] = a2;
    __syncthreads();
    if (tid < NH) {
        g_utt_e[c * NH + tid] = sp[0][tid] + sp[1][tid] + sp[2][tid] + sp[3][tid];
    }
    if (tid == 0) g_has_utt[c] = 1;
}

// ---------------- K6: fused mention segment softmax + final combine ----------------
__global__ void k_combine(const int* __restrict__ mids,
                          const float* __restrict__ w_comb, const float* __restrict__ b_comb,
                          float* __restrict__ out) {
    int c = blockIdx.x, tid = threadIdx.x;
    __shared__ int s_m[SCAP];
    __shared__ float s_w[SCAP];
    __shared__ int s_cnt;
    if (tid == 0) s_cnt = 0;
    __syncthreads();

    float lmax = NEGINF;
    for (int m = tid; m < NM; m += 256) {
        if (__ldg(&mids[m]) == c) {
            int p = atomicAdd(&s_cnt, 1);
            if (p < SCAP) {
                float sc = g_mscore[m];
                s_m[p] = m; s_w[p] = sc;
                lmax = fmaxf(lmax, sc);
            }
        }
    }
    lmax = blockReduceMax(lmax);
    int cnt = min(s_cnt, SCAP);

    float m0 = 0.f, m1 = 0.f, m2 = 0.f;
    int has_mention = (cnt > 0);
    if (cnt > 0) {
        float lsum = 0.f;
        for (int i = tid; i < cnt; i += 256) {
            float e = expf(s_w[i] - lmax);
            s_w[i] = e; lsum += e;
        }
        float tot = blockReduceSum(lsum);
        float inv = 1.f / tot;
        for (int i = 0; i < cnt; i++) {
            float w = s_w[i] * inv;
            const float* r = g_memb + (size_t)s_m[i] * NH;
            m0 += w * r[tid];
            m1 += w * r[tid + 256];
            m2 += w * r[tid + 512];
        }
    }

    float wc0 = __ldg(&w_comb[tid]), wc1 = __ldg(&w_comb[tid + 256]), wc2 = __ldg(&w_comb[tid + 512]);
    float n0 = g_name_e[c * NH + tid], n1 = g_name_e[c * NH + tid + 256], n2 = g_name_e[c * NH + tid + 512];
    float u0 = g_utt_e[c * NH + tid], u1 = g_utt_e[c * NH + tid + 256], u2 = g_utt_e[c * NH + tid + 512];

    float dn = blockReduceSum(n0 * wc0 + n1 * wc1 + n2 * wc2);
    float dm = blockReduceSum(m0 * wc0 + m1 * wc1 + m2 * wc2);
    float du = blockReduceSum(u0 * wc0 + u1 * wc1 + u2 * wc2);

    __shared__ float attn[3];
    if (tid == 0) {
        float bc = __ldg(b_comb);
        float s0 = dn + bc;
        float s1 = has_mention  ? (dm + bc) : NEGINF;
        float s2 = g_has_utt[c] ? (du + bc) : NEGINF;
        float mx = fmaxf(s0, fmaxf(s1, s2));
        float e0 = expf(s0 - mx);
        float e1 = (s1 > -1e30f) ? expf(s1 - mx) : 0.f;
        float e2 = (s2 > -1e30f) ? expf(s2 - mx) : 0.f;
        float inv = 1.f / (e0 + e1 + e2);
        attn[0] = e0 * inv; attn[1] = e1 * inv; attn[2] = e2 * inv;
    }
    __syncthreads();
    float A0 = attn[0], A1 = attn[1], A2 = attn[2];
    out[c * NH + tid]       = A0 * n0 + A1 * m0 + A2 * u0;
    out[c * NH + tid + 256] = A0 * n1 + A1 * m1 + A2 * u1;
    out[c * NH + tid + 512] = A0 * n2 + A1 * m2 + A2 * u2;
}

// ---------------- launch ----------------
extern "C" void kernel_launch(void* const* d_in, const int* in_sizes, int n_in,
                              void* d_out, int out_size) {
    const float* se        = (const float*)d_in[0];
    const float* nmask     = (const float*)d_in[1];
    const float* umask     = (const float*)d_in[2];
    const float* mmask     = (const float*)d_in[3];
    const int*   mids      = (const int*)  d_in[4];
    const float* w_name_tok = (const float*)d_in[5];
    const float* b_name_tok = (const float*)d_in[6];
    const float* w_name     = (const float*)d_in[7];
    const float* b_name     = (const float*)d_in[8];
    const float* w_men_tok  = (const float*)d_in[9];
    const float* b_men_tok  = (const float*)d_in[10];
    const float* w_men      = (const float*)d_in[11];
    const float* b_men      = (const float*)d_in[12];
    const float* w_utt      = (const float*)d_in[13];
    const float* b_utt      = (const float*)d_in[14];
    const float* w_comb     = (const float*)d_in[15];
    const float* b_comb     = (const float*)d_in[16];
    float* out = (float*)d_out;

    k_proj<<<NT / 8, 256>>>(se, w_name_tok, b_name_tok, w_men_tok, b_men_tok, w_utt, b_utt);
    k_names<<<NC * NB, 256>>>(nmask, w_name, b_name);
    k_name_e<<<NC, 1024>>>();
    k_mention<<<NM, 1024>>>(mmask, w_men, b_men);
    k_utt<<<NC, 1024>>>(umask);
    k_combine<<<NC, 256>>>(mids, w_comb, b_comb, out);
}